// round 1
// baseline (speedup 1.0000x reference)
#include <cuda_runtime.h>
#include <cstdint>

#define Tn   100
#define Fn   64
#define Hn   5
#define G2   10      // 4H/2 packed pairs
#define G4   20      // 4H
#define OUTn 3
#define BLK  128
#define ROWF 68      // padded floats per x row in smem (272B: conflict-free LDS.128)

typedef unsigned long long u64;

// ---------- f32x2 packed helpers ----------
__device__ __forceinline__ u64 pack2(float lo, float hi) {
    u64 r; asm("mov.b64 %0, {%1, %2};" : "=l"(r) : "f"(lo), "f"(hi)); return r;
}
__device__ __forceinline__ void unpack2(u64 v, float& lo, float& hi) {
    asm("mov.b64 {%0, %1}, %2;" : "=f"(lo), "=f"(hi) : "l"(v));
}
__device__ __forceinline__ u64 ffma2(u64 a, u64 b, u64 c) {
    u64 d; asm("fma.rn.f32x2 %0, %1, %2, %3;" : "=l"(d) : "l"(a), "l"(b), "l"(c));
    return d;
}

// ---------- fast gate math ----------
__device__ __forceinline__ float sigf(float x) {
    return __fdividef(1.0f, 1.0f + __expf(-x));
}
__device__ __forceinline__ float tanhfast(float x) {
    float ax = fabsf(x);
    float e  = __expf(-2.0f * ax);                  // e in (0,1], no overflow
    float r  = __fdividef(1.0f - e, 1.0f + e);
    return copysignf(r, x);
}

// accumulate 1 input feature into the 20 gate pre-activations (10 packed)
__device__ __forceinline__ void accum1(u64* acc, float xv, const u64* wrow) {
    u64 xx = pack2(xv, xv);
#pragma unroll
    for (int k2 = 0; k2 < 5; k2++) {
        ulonglong2 w = reinterpret_cast<const ulonglong2*>(wrow)[k2];
        acc[2 * k2]     = ffma2(xx, w.x, acc[2 * k2]);
        acc[2 * k2 + 1] = ffma2(xx, w.y, acc[2 * k2 + 1]);
    }
}

// accumulate a 5-vector (h or small input) through a [5,20] matrix
__device__ __forceinline__ void accum5(u64* acc, const float* h, const u64* Wp) {
#pragma unroll
    for (int j = 0; j < Hn; j++) {
        accum1(acc, h[j], Wp + j * G2);
    }
}

// apply LSTM gate nonlinearity, update h,c in place
__device__ __forceinline__ void gates(const u64* acc, float* h, float* c) {
    float z[G4];
#pragma unroll
    for (int k = 0; k < G2; k++) unpack2(acc[k], z[2 * k], z[2 * k + 1]);
#pragma unroll
    for (int j = 0; j < Hn; j++) {
        float ig = sigf(z[j]);
        float fg = sigf(z[Hn + j]);
        float gg = tanhfast(z[2 * Hn + j]);
        float og = sigf(z[3 * Hn + j]);
        float cn = fg * c[j] + ig * gg;
        c[j] = cn;
        h[j] = og * tanhfast(cn);
    }
}

extern "C" __global__ void __launch_bounds__(BLK, 1)
lstm3_kernel(const float* __restrict__ x,
             const float* __restrict__ W1, const float* __restrict__ U1, const float* __restrict__ b1,
             const float* __restrict__ W2, const float* __restrict__ U2, const float* __restrict__ b2,
             const float* __restrict__ W3, const float* __restrict__ U3, const float* __restrict__ b3,
             const float* __restrict__ Wd, const float* __restrict__ bd,
             float* __restrict__ out)
{
    __shared__ __align__(16) u64 sW1[Fn * G2];                       // 64x20 packed pairs
    __shared__ __align__(16) u64 sU1[Hn * G2], sW2[Hn * G2], sU2[Hn * G2];
    __shared__ __align__(16) u64 sW3[Hn * G2], sU3[Hn * G2];
    __shared__ __align__(16) u64 sb1[G2], sb2[G2], sb3[G2];
    __shared__ float sWd[Hn * OUTn];
    __shared__ float sbd[OUTn];
    extern __shared__ float xs[];  // 2 buffers of [BLK][ROWF]

    const int tid = threadIdx.x;
    const int b0  = blockIdx.x * BLK;

    // ---- stage weights into smem (packed f32x2 pairs) ----
    {
        const float2* g = reinterpret_cast<const float2*>(W1);
        float2* s = reinterpret_cast<float2*>(sW1);
        for (int i = tid; i < Fn * G2; i += BLK) s[i] = g[i];

        if (tid < Hn * G2) {
            reinterpret_cast<float2*>(sU1)[tid] = reinterpret_cast<const float2*>(U1)[tid];
            reinterpret_cast<float2*>(sW2)[tid] = reinterpret_cast<const float2*>(W2)[tid];
            reinterpret_cast<float2*>(sU2)[tid] = reinterpret_cast<const float2*>(U2)[tid];
            reinterpret_cast<float2*>(sW3)[tid] = reinterpret_cast<const float2*>(W3)[tid];
            reinterpret_cast<float2*>(sU3)[tid] = reinterpret_cast<const float2*>(U3)[tid];
        }
        if (tid < G2) {
            reinterpret_cast<float2*>(sb1)[tid] = reinterpret_cast<const float2*>(b1)[tid];
            reinterpret_cast<float2*>(sb2)[tid] = reinterpret_cast<const float2*>(b2)[tid];
            reinterpret_cast<float2*>(sb3)[tid] = reinterpret_cast<const float2*>(b3)[tid];
        }
        if (tid < Hn * OUTn) sWd[tid] = Wd[tid];
        if (tid < OUTn)      sbd[tid] = bd[tid];
    }

    // ---- cp.async loader: block loads x[b0..b0+127, t, 0:64], coalesced ----
    const int rowq = tid >> 4;   // 0..7
    const int colq = tid & 15;   // 0..15 (float4 index within a 64-float row)
    const uint32_t sm_base = (uint32_t)__cvta_generic_to_shared(xs);

#define ISSUE_X(t_, sel_)                                                          \
    do {                                                                            \
        uint32_t base_ = sm_base + (uint32_t)(sel_) * (BLK * ROWF * 4);             \
        _Pragma("unroll")                                                           \
        for (int p = 0; p < 16; p++) {                                              \
            int row_ = p * 8 + rowq;                                                \
            const float* g_ = x + ((size_t)(b0 + row_) * Tn + (t_)) * Fn + colq * 4;\
            uint32_t dst_ = base_ + (uint32_t)(row_ * ROWF * 4 + colq * 16);        \
            asm volatile("cp.async.cg.shared.global [%0], [%1], 16;"                \
                         :: "r"(dst_), "l"(g_));                                    \
        }                                                                           \
    } while (0)

    ISSUE_X(0, 0);
    asm volatile("cp.async.commit_group;");

    // ---- state ----
    float h1[Hn], c1[Hn], h2[Hn], c2[Hn], h3[Hn], c3[Hn];
#pragma unroll
    for (int j = 0; j < Hn; j++) {
        h1[j] = c1[j] = h2[j] = c2[j] = h3[j] = c3[j] = 0.0f;
    }

    for (int t = 0; t < Tn; t++) {
        const int cur = t & 1;
        if (t + 1 < Tn) {
            ISSUE_X(t + 1, cur ^ 1);
            asm volatile("cp.async.commit_group;");
            asm volatile("cp.async.wait_group 1;");
        } else {
            asm volatile("cp.async.wait_group 0;");
        }
        __syncthreads();   // buffer 'cur' fully visible (also covers weight staging at t=0)

        const float4* xr4 =
            reinterpret_cast<const float4*>(xs + cur * (BLK * ROWF) + tid * ROWF);

        u64 acc[G2];

        // ----- layer 1 -----
#pragma unroll
        for (int k = 0; k < G2; k++) acc[k] = sb1[k];
#pragma unroll
        for (int q = 0; q < 16; q++) {
            float4 xv = xr4[q];
            const u64* wrow = sW1 + (q * 4) * G2;
            accum1(acc, xv.x, wrow);
            accum1(acc, xv.y, wrow + G2);
            accum1(acc, xv.z, wrow + 2 * G2);
            accum1(acc, xv.w, wrow + 3 * G2);
        }
        accum5(acc, h1, sU1);
        gates(acc, h1, c1);

        // ----- layer 2 -----
#pragma unroll
        for (int k = 0; k < G2; k++) acc[k] = sb2[k];
        accum5(acc, h1, sW2);
        accum5(acc, h2, sU2);
        gates(acc, h2, c2);

        // ----- layer 3 -----
#pragma unroll
        for (int k = 0; k < G2; k++) acc[k] = sb3[k];
        accum5(acc, h2, sW3);
        accum5(acc, h3, sU3);
        gates(acc, h3, c3);

        __syncthreads();   // all threads done reading 'cur' before it is refilled
    }

    // ---- dense head: out[b,:] = h3 @ Wd + bd ----
    const int b = b0 + tid;
#pragma unroll
    for (int oc = 0; oc < OUTn; oc++) {
        float a = sbd[oc];
#pragma unroll
        for (int j = 0; j < Hn; j++) a += h3[j] * sWd[j * OUTn + oc];
        out[(size_t)b * OUTn + oc] = a;
    }
#undef ISSUE_X
}

extern "C" void kernel_launch(void* const* d_in, const int* in_sizes, int n_in,
                              void* d_out, int out_size)
{
    const float* x  = (const float*)d_in[0];
    const float* W1 = (const float*)d_in[1];
    const float* U1 = (const float*)d_in[2];
    const float* b1 = (const float*)d_in[3];
    const float* W2 = (const float*)d_in[4];
    const float* U2 = (const float*)d_in[5];
    const float* b2 = (const float*)d_in[6];
    const float* W3 = (const float*)d_in[7];
    const float* U3 = (const float*)d_in[8];
    const float* b3 = (const float*)d_in[9];
    const float* Wd = (const float*)d_in[10];
    const float* bd = (const float*)d_in[11];
    float* out = (float*)d_out;

    const int B = in_sizes[0] / (Tn * Fn);     // 16384
    const int smem = 2 * BLK * ROWF * 4;       // 69632 B double-buffered x

    cudaFuncSetAttribute(lstm3_kernel, cudaFuncAttributeMaxDynamicSharedMemorySize, smem);
    lstm3_kernel<<<B / BLK, BLK, smem>>>(x, W1, U1, b1, W2, U2, b2,
                                         W3, U3, b3, Wd, bd, out);
}